// round 16
// baseline (speedup 1.0000x reference)
#include <cuda_runtime.h>

#define B 16
#define G 5000
#define K 256
#define HID 64
#define NCHUNK 148
#define NG1 34            // genes/block in K1 (148*34 = 5032 >= 5000)
#define NG1P 36           // padded gene slots
#define GT 40             // genes/block in K3 (125 blocks)
#define K2GRID 128        // 16 APPNP CTAs + 112 pure A^2 helpers

typedef unsigned long long u64;

// Scratch (no allocations; counters monotone across replays => replay-safe)
__device__ __align__(16) float g_partial[NCHUNK][B][K];  // 2.4 MB
__device__ __align__(16) u64 g_Ap[128 * 256];            // (A[2p][k],A[2p+1][k])
__device__ __align__(16) u64 g_A2p[128 * 256];           // (A2[2p][k],A2[2p+1][k])
__device__ __align__(16) float g_Z[B][K];
__device__ float g_coff[B];
__device__ u64 g_c1, g_cA2;       // epoch counter / A2-ready counter

// ---- packed fp32x2 helpers (FFMA2 is PTX-only) ----
__device__ __forceinline__ u64 pack2(float x, float y) {
    u64 r; asm("mov.b64 %0, {%1, %2};" : "=l"(r) : "f"(x), "f"(y)); return r;
}
__device__ __forceinline__ void unpack2(u64 v, float& x, float& y) {
    asm("mov.b64 {%0, %1}, %2;" : "=f"(x), "=f"(y) : "l"(v));
}
__device__ __forceinline__ void ffma2(u64& acc, u64 a, u64 b) {
    asm("fma.rn.f32x2 %0, %1, %2, %0;" : "+l"(acc) : "l"(a), "l"(b));
}
__device__ __forceinline__ void lds_v2b64(unsigned a, u64& x, u64& y) {
    asm volatile("ld.shared.v2.b64 {%0, %1}, [%2];" : "=l"(x), "=l"(y) : "r"(a));
}
__device__ __forceinline__ void grid_dep_wait() {
    asm volatile("griddepcontrol.wait;" ::: "memory");
}

#define FMAXUPD(ACC, T, MV)                         \
    ACC.x = fmaxf(ACC.x, (T) * MV.x);               \
    ACC.y = fmaxf(ACC.y, (T) * MV.y);               \
    ACC.z = fmaxf(ACC.z, (T) * MV.z);               \
    ACC.w = fmaxf(ACC.w, (T) * MV.w);

// ---------------------------------------------------------------------------
// K1: max-pool (R12 verbatim, best-measured 8.8us). 148 blocks x 1024 thr.
// ---------------------------------------------------------------------------
__global__ __launch_bounds__(1024) void k1_maxpool(
    const float* __restrict__ t, const float* __restrict__ M)
{
    extern __shared__ float s1[];
    float*  ts   = s1;                         // ts4[gl][h] float4 = 576 floats
    float*  Ms   = s1 + 576;                   // [NG1P][256] = 9216
    float4* red4 = (float4*)(s1 + 576 + 9216); // [64][64] float4 = 64 KB

    const int tid = threadIdx.x;
    const int g0  = blockIdx.x * NG1;

    if (tid < NG1P * 16) {
        int gl = tid >> 4;
        int b  = tid & 15;
        int g  = g0 + gl;
        ts[gl * 16 + b] = (gl < NG1 && g < G) ? t[b * G + g] : 0.0f;
    }
    for (int i = tid; i < NG1P * 64; i += 1024) {
        int gl = i >> 6, jq = i & 63;
        int g = g0 + gl;
        float4 v = (gl < NG1 && g < G)
                 ? *(const float4*)(M + (size_t)g * K + 4 * jq)
                 : make_float4(0.f, 0.f, 0.f, 0.f);
        *(float4*)(Ms + gl * 256 + 4 * jq) = v;
    }
    __syncthreads();

    const int q4 = tid & 63;
    const int h  = (tid >> 6) & 3;
    const int ge = tid >> 8;

    const float4* MsV = (const float4*)Ms + ge * 64 + q4;
    const float4* TsV = (const float4*)ts + ge * 4 + h;

    float4 acc[4];
#pragma unroll
    for (int ii = 0; ii < 4; ii++) acc[ii] = make_float4(0.f, 0.f, 0.f, 0.f);

    float4 m  = MsV[0];
    float4 tq = TsV[0];
#pragma unroll
    for (int u = 0; u < 9; u++) {
        float4 mn, tn;
        if (u < 8) {
            mn = MsV[(u + 1) * 256];
            tn = TsV[(u + 1) * 16];
        }
        FMAXUPD(acc[0], tq.x, m)
        FMAXUPD(acc[1], tq.y, m)
        FMAXUPD(acc[2], tq.z, m)
        FMAXUPD(acc[3], tq.w, m)
        if (u < 8) { m = mn; tq = tn; }
    }

#pragma unroll
    for (int ii = 0; ii < 4; ii++)
        red4[(((ge * 4 + h) * 4 + ii) << 6) + q4] = acc[ii];
    __syncthreads();

    {
        const int q4r = tid & 63;
        const int b   = tid >> 6;
        const int hr  = b >> 2;
        const int ii  = b & 3;
        float4 a = red4[(((0 * 4 + hr) * 4 + ii) << 6) + q4r];
        float4 c = red4[(((1 * 4 + hr) * 4 + ii) << 6) + q4r];
        float4 d = red4[(((2 * 4 + hr) * 4 + ii) << 6) + q4r];
        float4 e = red4[(((3 * 4 + hr) * 4 + ii) << 6) + q4r];
        float4 r;
        r.x = fmaxf(fmaxf(a.x, c.x), fmaxf(d.x, e.x));
        r.y = fmaxf(fmaxf(a.y, c.y), fmaxf(d.y, e.y));
        r.z = fmaxf(fmaxf(a.z, c.z), fmaxf(d.z, e.z));
        r.w = fmaxf(fmaxf(a.w, c.w), fmaxf(d.w, e.w));
        *(float4*)(&g_partial[blockIdx.x][b][4 * q4r]) = r;
    }
}
#define K1_SMEM ((576 + 9216 + 64 * 64 * 4) * (int)sizeof(float))

// ---------------------------------------------------------------------------
// K2: grid 128. ALL CTAs first compute A^2 rows 2c,2c+1 + pair-pack A
// (runs in K1's drain window, off the critical path), publish, bump g_cA2.
// CTAs >= 16 exit. CTAs 0..15: spin for 128 publications (epoch-safe),
// preload regA2 + cell offset, grid_dep_wait, t_mod, then the validated
// 6-step sequence: Z1 = 0.9*S@A + 0.1*S; T2 = 0.1*Z1 + 0.09*S;
// 4x (Z <- 0.81*Z@A2 + T2); Z10 = 0.9*Z9@A + 0.1*S.
// ---------------------------------------------------------------------------
__global__ __launch_bounds__(1024, 1) void k2_appnp(
    const float* __restrict__ A,
    const int*   __restrict__ cell_idx,
    const float* __restrict__ cell_emb,
    const float* __restrict__ W2,
    const float* __restrict__ b2)
{
    __shared__ __align__(16) float Zs[256];
    __shared__ float Ss[256], T2s[256];
    __shared__ float pred[1024];
    __shared__ float As2[512];           // rows 2c, 2c+1 of A
    __shared__ float part[8 * 512];      // [lc][i][k] partials
    __shared__ float A2s[512];

    const int tid = threadIdx.x;
    const int c   = blockIdx.x;

    u64 L = 0;
    if (tid == 0) L = atomicAdd(&g_c1, 1ULL) / (u64)K2GRID;

    // ---- A^2 rows 2c, 2c+1 (contiguous: A[2c*K .. 2c*K+512)) ----
    if (tid < 512) As2[tid] = A[(size_t)(2 * c) * K + tid];
    __syncthreads();

    {
        const int lc = tid >> 7;         // 0..7
        const int k2 = tid & 127;        // k-pair
        float a00 = 0.f, a01 = 0.f, a10 = 0.f, a11 = 0.f;
#pragma unroll 8
        for (int u = 0; u < 32; u++) {
            int l = 32 * lc + u;
            float2 av = *(const float2*)(A + l * K + 2 * k2);
            float w0 = As2[l], w1 = As2[256 + l];
            a00 = fmaf(w0, av.x, a00);
            a01 = fmaf(w0, av.y, a01);
            a10 = fmaf(w1, av.x, a10);
            a11 = fmaf(w1, av.y, a11);
        }
        part[lc * 512 + 2 * k2]           = a00;
        part[lc * 512 + 2 * k2 + 1]       = a01;
        part[lc * 512 + 256 + 2 * k2]     = a10;
        part[lc * 512 + 256 + 2 * k2 + 1] = a11;
    }
    __syncthreads();

    if (tid < 512) {
        float s = 0.f;
#pragma unroll
        for (int lc = 0; lc < 8; lc++)
            s += part[lc * 512 + tid];
        A2s[tid] = s;
    }
    __syncthreads();

    if (tid < 256) {
        g_A2p[c * 256 + tid] = pack2(A2s[tid], A2s[256 + tid]);
    } else if (tid < 512) {
        int k = tid - 256;
        g_Ap[c * 256 + k] = pack2(As2[k], As2[256 + k]);
    }
    __threadfence();
    __syncthreads();
    if (tid == 0) atomicAdd(&g_cA2, 1ULL);

    if (c >= B) return;                  // helpers done

    // ==================== APPNP (CTAs 0..15) ====================
    const int b = c;
    const int q = tid >> 8;
    const int k = tid & 255;

    // spin until all 128 slices published (this launch's epoch)
    if (tid == 0) {
        u64 tgt = (L + 1) * (u64)K2GRID;
        while (*(volatile u64*)&g_cA2 < tgt) __nanosleep(32);
        __threadfence();
    }
    __syncthreads();

    // pre-wait: register-cached A2 pairs p = 32q+10 .. 32q+31
    u64 regA2[22];
#pragma unroll
    for (int u = 0; u < 22; u++)
        regA2[u] = g_A2p[(32 * q + 10 + u) * 256 + k];

    // pre-wait: cell offset
    if (tid >= 992) {
        int lane = tid - 992;
        int ci = cell_idx[b];
        float v = cell_emb[ci * HID + lane] * W2[lane]
                + cell_emb[ci * HID + 32 + lane] * W2[32 + lane];
#pragma unroll
        for (int o = 16; o > 0; o >>= 1)
            v += __shfl_down_sync(0xffffffffu, v, o);
        if (lane == 0) g_coff[b] = v + b2[0];
    }

    grid_dep_wait();    // K1 done: g_partial valid

    // t_mod reduction
    {
        float mv = 0.0f;
        const float* gp = &g_partial[q * 37][b][k];
#pragma unroll
        for (int cc = 0; cc < 37; cc++)
            mv = fmaxf(mv, gp[cc * (B * K)]);
        pred[tid] = mv;
    }
    __syncthreads();
    const float s_k = fmaxf(fmaxf(pred[k], pred[256 + k]),
                            fmaxf(pred[512 + k], pred[768 + k]));
    if (q == 0) { Ss[k] = s_k; Zs[k] = s_k; }
    __syncthreads();

    const unsigned zaddr = (unsigned)__cvta_generic_to_shared(Zs) + 256 * q;
    const u64* ApQ = g_Ap  + (32 * q) * 256 + k;
    const u64* A2Q = g_A2p + (32 * q) * 256 + k;

    // ---- Step 1: Z1 = 0.9*S@A + 0.1*S;  T2 = 0.1*Z1 + 0.09*S ----
    {
        u64 acc = 0;
#pragma unroll
        for (int i = 0; i < 16; i++) {
            u64 z0, z1;
            lds_v2b64(zaddr + 16 * i, z0, z1);
            ffma2(acc, ApQ[(2 * i) << 8], z0);
            ffma2(acc, ApQ[(2 * i + 1) << 8], z1);
        }
        float lo, hi;
        unpack2(acc, lo, hi);
        pred[tid] = lo + hi;
        __syncthreads();
        if (q == 0) {
            float v = (pred[k] + pred[256 + k]) + (pred[512 + k] + pred[768 + k]);
            float z1v = fmaf(0.9f, v, 0.1f * Ss[k]);
            Zs[k]  = z1v;
            T2s[k] = fmaf(0.1f, z1v, 0.09f * Ss[k]);
        }
        __syncthreads();
    }

    // ---- 4 double-steps: Z <- 0.81*Z@A2 + T2 ----
#pragma unroll 1
    for (int ss = 0; ss < 4; ss++) {
        u64 acc = 0;
#pragma unroll
        for (int i = 0; i < 5; i++) {          // L2 pairs 0..9
            u64 z0, z1;
            lds_v2b64(zaddr + 16 * i, z0, z1);
            ffma2(acc, A2Q[(2 * i) << 8], z0);
            ffma2(acc, A2Q[(2 * i + 1) << 8], z1);
        }
#pragma unroll
        for (int i = 0; i < 11; i++) {         // reg pairs 10..31
            u64 z0, z1;
            lds_v2b64(zaddr + 80 + 16 * i, z0, z1);
            ffma2(acc, regA2[2 * i], z0);
            ffma2(acc, regA2[2 * i + 1], z1);
        }
        float lo, hi;
        unpack2(acc, lo, hi);
        pred[tid] = lo + hi;
        __syncthreads();
        if (q == 0) {
            float v = (pred[k] + pred[256 + k]) + (pred[512 + k] + pred[768 + k]);
            Zs[k] = fmaf(0.81f, v, T2s[k]);
        }
        __syncthreads();
    }

    // ---- Final step: Z10 = 0.9*Z9@A + 0.1*S ----
    {
        u64 acc = 0;
#pragma unroll
        for (int i = 0; i < 16; i++) {
            u64 z0, z1;
            lds_v2b64(zaddr + 16 * i, z0, z1);
            ffma2(acc, ApQ[(2 * i) << 8], z0);
            ffma2(acc, ApQ[(2 * i + 1) << 8], z1);
        }
        float lo, hi;
        unpack2(acc, lo, hi);
        pred[tid] = lo + hi;
        __syncthreads();
        if (q == 0) {
            float v = (pred[k] + pred[256 + k]) + (pred[512 + k] + pred[768 + k]);
            g_Z[b][k] = fmaf(0.9f, v, 0.1f * Ss[k]);
        }
    }
}

// ---------------------------------------------------------------------------
// K3: z_gene + MLP + out (R12 verbatim). 125 blocks x 1024 threads.
// ---------------------------------------------------------------------------
#define K3_MS     0
#define K3_Z4     10280
#define K3_ZPART  14376
#define K3_WPACK  18216
#define K3_W2S    18472
#define K3_CTS    18536
#define K3_TTS    19176
#define K3_COFF   19816
#define K3_ZFIN   19832
#define K3_YPART  20472
#define K3_FLOATS 21752

__global__ __launch_bounds__(1024) void k3_out(
    const float* __restrict__ ctl,
    const float* __restrict__ t,
    const float* __restrict__ M,
    const float* __restrict__ W1,
    const float* __restrict__ b1,
    const float* __restrict__ W2,
    float* __restrict__ out)
{
    extern __shared__ float s3[];
    float*  Ms     = s3 + K3_MS;
    float4* Z4     = (float4*)(s3 + K3_Z4);
    float4* zpart  = (float4*)(s3 + K3_ZPART);
    float4* wpack  = (float4*)(s3 + K3_WPACK);
    float*  W2s    = s3 + K3_W2S;
    float*  cts    = s3 + K3_CTS;
    float*  tts    = s3 + K3_TTS;
    float*  coffs  = s3 + K3_COFF;
    float*  zfin   = s3 + K3_ZFIN;
    float2* ypart  = (float2*)(s3 + K3_YPART);

    const int tid = threadIdx.x;
    const int g0  = blockIdx.x * GT;

    for (int i = tid; i < GT * 64; i += 1024) {
        int gl = i >> 6, jq = i & 63;
        int g = g0 + gl;
        float4 v = (g < G) ? *(const float4*)(M + (size_t)g * K + 4 * jq)
                           : make_float4(0.f, 0.f, 0.f, 0.f);
        float* d = Ms + gl * 257 + 4 * jq;
        d[0] = v.x; d[1] = v.y; d[2] = v.z; d[3] = v.w;
    }
    if (tid < 64) {
        wpack[tid] = make_float4(W1[tid], W1[HID + tid], W1[2 * HID + tid], b1[tid]);
        W2s[tid]   = W2[tid];
    }
    if (tid < B * GT) {
        int bb = tid / GT, gl = tid % GT;
        int g = g0 + gl;
        cts[tid] = (g < G) ? ctl[bb * G + g] : 0.0f;
        tts[tid] = (g < G) ? t[bb * G + g] : 0.0f;
    }

    grid_dep_wait();

    {
        int p4 = tid >> 8, j = tid & 255;
        float4 zz;
        zz.x = g_Z[4 * p4 + 0][j];
        zz.y = g_Z[4 * p4 + 1][j];
        zz.z = g_Z[4 * p4 + 2][j];
        zz.w = g_Z[4 * p4 + 3][j];
        Z4[j * 4 + p4] = zz;
    }
    if (tid < B) coffs[tid] = g_coff[tid];
    __syncthreads();

    if (tid < 960) {
        const int jh = tid / 160;
        const int r  = tid - jh * 160;
        const int p4 = r / 40;
        const int gl = r - p4 * 40;
        const int j0 = (jh <= 4) ? jh * 43 : 214;
        const int j1 = (jh <= 3) ? j0 + 43 : j0 + 42;
        const float* Mrow = Ms + gl * 257;
        float4 acc = make_float4(0.f, 0.f, 0.f, 0.f);
        for (int j = j0; j < j1; j++) {
            float  m = Mrow[j];
            float4 z = Z4[j * 4 + p4];
            acc.x = fmaf(m, z.x, acc.x);
            acc.y = fmaf(m, z.y, acc.y);
            acc.z = fmaf(m, z.z, acc.z);
            acc.w = fmaf(m, z.w, acc.w);
        }
        zpart[(jh * 4 + p4) * 40 + gl] = acc;
    }
    __syncthreads();

    if (tid < 160) {
        int p4 = tid / 40, gl = tid - p4 * 40;
        float4 s = make_float4(0.f, 0.f, 0.f, 0.f);
#pragma unroll
        for (int jh = 0; jh < 6; jh++) {
            float4 v = zpart[(jh * 4 + p4) * 40 + gl];
            s.x += v.x; s.y += v.y; s.z += v.z; s.w += v.w;
        }
        zfin[(4 * p4 + 0) * 40 + gl] = s.x;
        zfin[(4 * p4 + 1) * 40 + gl] = s.y;
        zfin[(4 * p4 + 2) * 40 + gl] = s.z;
        zfin[(4 * p4 + 3) * 40 + gl] = s.w;
    }
    __syncthreads();

    if (tid < 640) {
        const int jh2 = tid / 320;
        const int r   = tid - jh2 * 320;
        const int p   = r / 40;
        const int gl  = r - p * 40;
        float z0 = zfin[p * 40 + gl],  z1 = zfin[(p + 8) * 40 + gl];
        float c0 = cts[p * 40 + gl],   c1 = cts[(p + 8) * 40 + gl];
        float t0 = tts[p * 40 + gl],   t1 = tts[(p + 8) * 40 + gl];
        float y0 = 0.f, y1 = 0.f;
#pragma unroll
        for (int jj = 0; jj < 32; jj++) {
            int j = 32 * jh2 + jj;
            float4 w = wpack[j];
            float  w2 = W2s[j];
            float v0 = fmaf(c0, w.x, fmaf(t0, w.y, fmaf(z0, w.z, w.w)));
            float v1 = fmaf(c1, w.x, fmaf(t1, w.y, fmaf(z1, w.z, w.w)));
            y0 = fmaf(fmaxf(v0, 0.f), w2, y0);
            y1 = fmaf(fmaxf(v1, 0.f), w2, y1);
        }
        ypart[jh2 * 320 + r] = make_float2(y0, y1);
    }
    __syncthreads();

    if (tid < 320) {
        int p = tid / 40, gl = tid - p * 40;
        int g = g0 + gl;
        if (g < G) {
            float2 a = ypart[tid], bb = ypart[320 + tid];
            out[p * G + g]       = (a.x + bb.x) + coffs[p];
            out[(p + 8) * G + g] = (a.y + bb.y) + coffs[p + 8];
        }
    }
}
#define K3_SMEM (K3_FLOATS * (int)sizeof(float))

// ---------------------------------------------------------------------------
// metadata order: ctl, drug_targets, cell_idx, drug_fp, M, A, W1, b1,
//                 cell_emb, W2, b2   -> output [B, G] float32
// ---------------------------------------------------------------------------
extern "C" void kernel_launch(void* const* d_in, const int* in_sizes, int n_in,
                              void* d_out, int out_size)
{
    const float* ctl      = (const float*)d_in[0];
    const float* tgt      = (const float*)d_in[1];
    const int*   cell_idx = (const int*)  d_in[2];
    // d_in[3] = drug_fp (unused by the model)
    const float* M        = (const float*)d_in[4];
    const float* A        = (const float*)d_in[5];
    const float* W1       = (const float*)d_in[6];
    const float* b1       = (const float*)d_in[7];
    const float* cell_emb = (const float*)d_in[8];
    const float* W2       = (const float*)d_in[9];
    const float* b2       = (const float*)d_in[10];
    float* out = (float*)d_out;

    cudaFuncSetAttribute(k1_maxpool,
                         cudaFuncAttributeMaxDynamicSharedMemorySize, K1_SMEM);
    cudaFuncSetAttribute(k3_out,
                         cudaFuncAttributeMaxDynamicSharedMemorySize, K3_SMEM);

    k1_maxpool<<<NCHUNK, 1024, K1_SMEM>>>(tgt, M);

    cudaLaunchAttribute pdl[1];
    pdl[0].id = cudaLaunchAttributeProgrammaticStreamSerialization;
    pdl[0].val.programmaticStreamSerializationAllowed = 1;

    {
        cudaLaunchConfig_t cfg = {};
        cfg.gridDim = dim3(K2GRID, 1, 1);
        cfg.blockDim = dim3(1024, 1, 1);
        cfg.dynamicSmemBytes = 0;
        cfg.attrs = pdl;
        cfg.numAttrs = 1;
        cudaLaunchKernelEx(&cfg, k2_appnp, A, cell_idx, cell_emb, W2, b2);
    }
    {
        cudaLaunchConfig_t cfg = {};
        cfg.gridDim = dim3((G + GT - 1) / GT, 1, 1);   // 125
        cfg.blockDim = dim3(1024, 1, 1);
        cfg.dynamicSmemBytes = K3_SMEM;
        cfg.attrs = pdl;
        cfg.numAttrs = 1;
        cudaLaunchKernelEx(&cfg, k3_out, ctl, tgt, M, W1, b1, W2, out);
    }
}

// round 17
// speedup vs baseline: 1.2193x; 1.2193x over previous
#include <cuda_runtime.h>

#define B 16
#define G 5000
#define K 256
#define HID 64
#define STEPS 10
#define NCHUNK 148
#define NG1 34            // genes/block in K1 (148*34 = 5032 >= 5000)
#define NG1P 36           // padded gene slots
#define GT 40             // genes/block in K3 (125 blocks)

typedef unsigned long long u64;

// Scratch (no allocations allowed)
__device__ __align__(16) float g_partial[NCHUNK][B][K];  // 2.4 MB
__device__ __align__(16) float g_Z[B][K];
__device__ float g_coff[B];

// ---- packed fp32x2 helpers (FFMA2 is PTX-only) ----
__device__ __forceinline__ u64 pack2(float x, float y) {
    u64 r; asm("mov.b64 %0, {%1, %2};" : "=l"(r) : "f"(x), "f"(y)); return r;
}
__device__ __forceinline__ void unpack2(u64 v, float& x, float& y) {
    asm("mov.b64 {%0, %1}, %2;" : "=f"(x), "=f"(y) : "l"(v));
}
__device__ __forceinline__ void ffma2(u64& acc, u64 a, u64 b) {
    asm("fma.rn.f32x2 %0, %1, %2, %0;" : "+l"(acc) : "l"(a), "l"(b));
}
__device__ __forceinline__ u64 lds_b64(unsigned a) {
    u64 r; asm volatile("ld.shared.b64 %0, [%1];" : "=l"(r) : "r"(a)); return r;
}
__device__ __forceinline__ void lds_v2b64(unsigned a, u64& x, u64& y) {
    asm volatile("ld.shared.v2.b64 {%0, %1}, [%2];" : "=l"(x), "=l"(y) : "r"(a));
}
__device__ __forceinline__ void sts_b64(unsigned a, u64 v) {
    asm volatile("st.shared.b64 [%0], %1;" :: "r"(a), "l"(v) : "memory");
}
__device__ __forceinline__ void grid_dep_wait() {
    asm volatile("griddepcontrol.wait;" ::: "memory");
}

#define FMAXUPD(ACC, T, MV)                         \
    ACC.x = fmaxf(ACC.x, (T) * MV.x);               \
    ACC.y = fmaxf(ACC.y, (T) * MV.y);               \
    ACC.z = fmaxf(ACC.z, (T) * MV.z);               \
    ACC.w = fmaxf(ACC.w, (T) * MV.w);

// ---------------------------------------------------------------------------
// K1: max-pool (R12 verbatim, 8.8us measured). 148 blocks x 1024 threads.
// ---------------------------------------------------------------------------
__global__ __launch_bounds__(1024) void k1_maxpool(
    const float* __restrict__ t, const float* __restrict__ M)
{
    extern __shared__ float s1[];
    float*  ts   = s1;                         // ts4[gl][h] float4 = 576 floats
    float*  Ms   = s1 + 576;                   // [NG1P][256] = 9216
    float4* red4 = (float4*)(s1 + 576 + 9216); // [64][64] float4 = 64 KB

    const int tid = threadIdx.x;
    const int g0  = blockIdx.x * NG1;

    if (tid < NG1P * 16) {
        int gl = tid >> 4;
        int b  = tid & 15;
        int g  = g0 + gl;
        ts[gl * 16 + b] = (gl < NG1 && g < G) ? t[b * G + g] : 0.0f;
    }
    for (int i = tid; i < NG1P * 64; i += 1024) {
        int gl = i >> 6, jq = i & 63;
        int g = g0 + gl;
        float4 v = (gl < NG1 && g < G)
                 ? *(const float4*)(M + (size_t)g * K + 4 * jq)
                 : make_float4(0.f, 0.f, 0.f, 0.f);
        *(float4*)(Ms + gl * 256 + 4 * jq) = v;
    }
    __syncthreads();

    const int q4 = tid & 63;
    const int h  = (tid >> 6) & 3;
    const int ge = tid >> 8;

    const float4* MsV = (const float4*)Ms + ge * 64 + q4;
    const float4* TsV = (const float4*)ts + ge * 4 + h;

    float4 acc[4];
#pragma unroll
    for (int ii = 0; ii < 4; ii++) acc[ii] = make_float4(0.f, 0.f, 0.f, 0.f);

    float4 m  = MsV[0];
    float4 tq = TsV[0];
#pragma unroll
    for (int u = 0; u < 9; u++) {
        float4 mn, tn;
        if (u < 8) {
            mn = MsV[(u + 1) * 256];
            tn = TsV[(u + 1) * 16];
        }
        FMAXUPD(acc[0], tq.x, m)
        FMAXUPD(acc[1], tq.y, m)
        FMAXUPD(acc[2], tq.z, m)
        FMAXUPD(acc[3], tq.w, m)
        if (u < 8) { m = mn; tq = tn; }
    }

#pragma unroll
    for (int ii = 0; ii < 4; ii++)
        red4[(((ge * 4 + h) * 4 + ii) << 6) + q4] = acc[ii];
    __syncthreads();

    {
        const int q4r = tid & 63;
        const int b   = tid >> 6;
        const int hr  = b >> 2;
        const int ii  = b & 3;
        float4 a = red4[(((0 * 4 + hr) * 4 + ii) << 6) + q4r];
        float4 c = red4[(((1 * 4 + hr) * 4 + ii) << 6) + q4r];
        float4 d = red4[(((2 * 4 + hr) * 4 + ii) << 6) + q4r];
        float4 e = red4[(((3 * 4 + hr) * 4 + ii) << 6) + q4r];
        float4 r;
        r.x = fmaxf(fmaxf(a.x, c.x), fmaxf(d.x, e.x));
        r.y = fmaxf(fmaxf(a.y, c.y), fmaxf(d.y, e.y));
        r.z = fmaxf(fmaxf(a.z, c.z), fmaxf(d.z, e.z));
        r.w = fmaxf(fmaxf(a.w, c.w), fmaxf(d.w, e.w));
        *(float4*)(&g_partial[blockIdx.x][b][4 * q4r]) = r;
    }
}
#define K1_SMEM ((576 + 9216 + 64 * 64 * 4) * (int)sizeof(float))

// ---------------------------------------------------------------------------
// K2: APPNP, 16 blocks x 512 threads (reg cap 128). Thread (q = tid>>8, k =
// tid&255) owns j in [128q, 128q+128) as 64 pairs: pairs 0..15 in smem
// (rows q*16+i), pairs 16..63 in 48 u64 registers. 10 steps, 16-warp
// barriers, 2-way reduce. smem: Apairs 64KB | Zs 1KB | pred 2KB.
// ---------------------------------------------------------------------------
#define K2_ASM_BYTES (32 * 256 * 8)
#define K2_SMEM_BYTES (K2_ASM_BYTES + 1024 + 2048)

__global__ __launch_bounds__(512, 1) void k2_appnp(
    const float* __restrict__ A,
    const int*   __restrict__ cell_idx,
    const float* __restrict__ cell_emb,
    const float* __restrict__ W2,
    const float* __restrict__ b2)
{
    extern __shared__ float sm[];
    float* Zs   = sm + K2_ASM_BYTES / 4;           // 256 floats
    float* pred = Zs + 256;                         // 512 floats
    const unsigned abase = (unsigned)__cvta_generic_to_shared(sm);
    const unsigned zbase = abase + K2_ASM_BYTES;

    const int tid = threadIdx.x;
    const int b   = blockIdx.x;
    const int q   = tid >> 8;                       // 0..1
    const int k   = tid & 255;

    // --- register A pairs: j in [128q+32, 128q+128), 48 pairs ---
    u64 regA2[48];
#pragma unroll
    for (int u = 0; u < 48; u++) {
        int j0 = 128 * q + 32 + 2 * u;
        regA2[u] = pack2(A[j0 * K + k], A[(j0 + 1) * K + k]);
    }

    // --- smem A pairs: row r = q2*16 + i holds pair j0 = 128*q2 + 2i ---
    for (int idx = tid; idx < 32 * 256; idx += 512) {
        int r = idx >> 8, kk = idx & 255;
        int q2 = r >> 4, i = r & 15;
        int j0 = 128 * q2 + 2 * i;
        sts_b64(abase + (unsigned)(idx * 8),
                pack2(A[j0 * K + kk], A[j0 * K + K + kk]));
    }

    // --- cell offset: top warp ---
    if (tid >= 480) {
        int lane = tid - 480;
        int ci = cell_idx[b];
        float v = cell_emb[ci * HID + lane] * W2[lane]
                + cell_emb[ci * HID + 32 + lane] * W2[32 + lane];
#pragma unroll
        for (int o = 16; o > 0; o >>= 1)
            v += __shfl_down_sync(0xffffffffu, v, o);
        if (lane == 0) g_coff[b] = v + b2[0];
    }

    grid_dep_wait();

    // --- t_mod reduction: 74 chunks per q-group, dual accumulators ---
    {
        float m0 = 0.0f, m1 = 0.0f;
        const float* gp = &g_partial[q * 74][b][k];
#pragma unroll
        for (int c = 0; c < 74; c += 2) {
            m0 = fmaxf(m0, gp[c * (B * K)]);
            m1 = fmaxf(m1, gp[(c + 1) * (B * K)]);
        }
        pred[tid] = fmaxf(m0, m1);
    }
    __syncthreads();

    const float s_k = fmaxf(pred[k], pred[256 + k]);
    if (q == 0) Zs[k] = s_k;
    __syncthreads();

    const unsigned zq  = zbase + (unsigned)(512 * q);         // floats 128q..
    const unsigned aTh = abase + (unsigned)(((q * 16) * 256 + k) * 8);

#pragma unroll 1
    for (int s = 0; s < STEPS; s++) {
        u64 acc = 0;
#pragma unroll
        for (int i = 0; i < 8; i++) {          // smem pairs 0..15
            u64 z0, z1;
            lds_v2b64(zq + 16 * i, z0, z1);
            u64 a0 = lds_b64(aTh + (unsigned)((2 * i) * 2048));
            u64 a1 = lds_b64(aTh + (unsigned)((2 * i + 1) * 2048));
            ffma2(acc, a0, z0);
            ffma2(acc, a1, z1);
        }
#pragma unroll
        for (int i = 0; i < 24; i++) {         // reg pairs 16..63
            u64 z0, z1;
            lds_v2b64(zq + 128 + 16 * i, z0, z1);
            ffma2(acc, regA2[2 * i], z0);
            ffma2(acc, regA2[2 * i + 1], z1);
        }
        float lo, hi;
        unpack2(acc, lo, hi);
        pred[tid] = lo + hi;
        __syncthreads();
        float v = pred[k] + pred[256 + k];
        float zn = fmaf(0.9f, v, 0.1f * s_k);
        if (q == 0) Zs[k] = zn;
        __syncthreads();
    }

    if (q == 0) g_Z[b][k] = Zs[k];
}

// ---------------------------------------------------------------------------
// K3: z_gene + MLP + out (R12 verbatim). 125 blocks x 1024 threads.
// ---------------------------------------------------------------------------
#define K3_MS     0
#define K3_Z4     10280
#define K3_ZPART  14376
#define K3_WPACK  18216
#define K3_W2S    18472
#define K3_CTS    18536
#define K3_TTS    19176
#define K3_COFF   19816
#define K3_ZFIN   19832
#define K3_YPART  20472
#define K3_FLOATS 21752

__global__ __launch_bounds__(1024) void k3_out(
    const float* __restrict__ ctl,
    const float* __restrict__ t,
    const float* __restrict__ M,
    const float* __restrict__ W1,
    const float* __restrict__ b1,
    const float* __restrict__ W2,
    float* __restrict__ out)
{
    extern __shared__ float s3[];
    float*  Ms     = s3 + K3_MS;
    float4* Z4     = (float4*)(s3 + K3_Z4);
    float4* zpart  = (float4*)(s3 + K3_ZPART);
    float4* wpack  = (float4*)(s3 + K3_WPACK);
    float*  W2s    = s3 + K3_W2S;
    float*  cts    = s3 + K3_CTS;
    float*  tts    = s3 + K3_TTS;
    float*  coffs  = s3 + K3_COFF;
    float*  zfin   = s3 + K3_ZFIN;
    float2* ypart  = (float2*)(s3 + K3_YPART);

    const int tid = threadIdx.x;
    const int g0  = blockIdx.x * GT;

    for (int i = tid; i < GT * 64; i += 1024) {
        int gl = i >> 6, jq = i & 63;
        int g = g0 + gl;
        float4 v = (g < G) ? *(const float4*)(M + (size_t)g * K + 4 * jq)
                           : make_float4(0.f, 0.f, 0.f, 0.f);
        float* d = Ms + gl * 257 + 4 * jq;
        d[0] = v.x; d[1] = v.y; d[2] = v.z; d[3] = v.w;
    }
    if (tid < 64) {
        wpack[tid] = make_float4(W1[tid], W1[HID + tid], W1[2 * HID + tid], b1[tid]);
        W2s[tid]   = W2[tid];
    }
    if (tid < B * GT) {
        int bb = tid / GT, gl = tid % GT;
        int g = g0 + gl;
        cts[tid] = (g < G) ? ctl[bb * G + g] : 0.0f;
        tts[tid] = (g < G) ? t[bb * G + g] : 0.0f;
    }

    grid_dep_wait();

    {
        int p4 = tid >> 8, j = tid & 255;
        float4 zz;
        zz.x = g_Z[4 * p4 + 0][j];
        zz.y = g_Z[4 * p4 + 1][j];
        zz.z = g_Z[4 * p4 + 2][j];
        zz.w = g_Z[4 * p4 + 3][j];
        Z4[j * 4 + p4] = zz;
    }
    if (tid < B) coffs[tid] = g_coff[tid];
    __syncthreads();

    if (tid < 960) {
        const int jh = tid / 160;
        const int r  = tid - jh * 160;
        const int p4 = r / 40;
        const int gl = r - p4 * 40;
        const int j0 = (jh <= 4) ? jh * 43 : 214;
        const int j1 = (jh <= 3) ? j0 + 43 : j0 + 42;
        const float* Mrow = Ms + gl * 257;
        float4 acc = make_float4(0.f, 0.f, 0.f, 0.f);
        for (int j = j0; j < j1; j++) {
            float  m = Mrow[j];
            float4 z = Z4[j * 4 + p4];
            acc.x = fmaf(m, z.x, acc.x);
            acc.y = fmaf(m, z.y, acc.y);
            acc.z = fmaf(m, z.z, acc.z);
            acc.w = fmaf(m, z.w, acc.w);
        }
        zpart[(jh * 4 + p4) * 40 + gl] = acc;
    }
    __syncthreads();

    if (tid < 160) {
        int p4 = tid / 40, gl = tid - p4 * 40;
        float4 s = make_float4(0.f, 0.f, 0.f, 0.f);
#pragma unroll
        for (int jh = 0; jh < 6; jh++) {
            float4 v = zpart[(jh * 4 + p4) * 40 + gl];
            s.x += v.x; s.y += v.y; s.z += v.z; s.w += v.w;
        }
        zfin[(4 * p4 + 0) * 40 + gl] = s.x;
        zfin[(4 * p4 + 1) * 40 + gl] = s.y;
        zfin[(4 * p4 + 2) * 40 + gl] = s.z;
        zfin[(4 * p4 + 3) * 40 + gl] = s.w;
    }
    __syncthreads();

    if (tid < 640) {
        const int jh2 = tid / 320;
        const int r   = tid - jh2 * 320;
        const int p   = r / 40;
        const int gl  = r - p * 40;
        float z0 = zfin[p * 40 + gl],  z1 = zfin[(p + 8) * 40 + gl];
        float c0 = cts[p * 40 + gl],   c1 = cts[(p + 8) * 40 + gl];
        float t0 = tts[p * 40 + gl],   t1 = tts[(p + 8) * 40 + gl];
        float y0 = 0.f, y1 = 0.f;
#pragma unroll
        for (int jj = 0; jj < 32; jj++) {
            int j = 32 * jh2 + jj;
            float4 w = wpack[j];
            float  w2 = W2s[j];
            float v0 = fmaf(c0, w.x, fmaf(t0, w.y, fmaf(z0, w.z, w.w)));
            float v1 = fmaf(c1, w.x, fmaf(t1, w.y, fmaf(z1, w.z, w.w)));
            y0 = fmaf(fmaxf(v0, 0.f), w2, y0);
            y1 = fmaf(fmaxf(v1, 0.f), w2, y1);
        }
        ypart[jh2 * 320 + r] = make_float2(y0, y1);
    }
    __syncthreads();

    if (tid < 320) {
        int p = tid / 40, gl = tid - p * 40;
        int g = g0 + gl;
        if (g < G) {
            float2 a = ypart[tid], bb = ypart[320 + tid];
            out[p * G + g]       = (a.x + bb.x) + coffs[p];
            out[(p + 8) * G + g] = (a.y + bb.y) + coffs[p + 8];
        }
    }
}
#define K3_SMEM (K3_FLOATS * (int)sizeof(float))

// ---------------------------------------------------------------------------
// metadata order: ctl, drug_targets, cell_idx, drug_fp, M, A, W1, b1,
//                 cell_emb, W2, b2   -> output [B, G] float32
// ---------------------------------------------------------------------------
extern "C" void kernel_launch(void* const* d_in, const int* in_sizes, int n_in,
                              void* d_out, int out_size)
{
    const float* ctl      = (const float*)d_in[0];
    const float* tgt      = (const float*)d_in[1];
    const int*   cell_idx = (const int*)  d_in[2];
    // d_in[3] = drug_fp (unused by the model)
    const float* M        = (const float*)d_in[4];
    const float* A        = (const float*)d_in[5];
    const float* W1       = (const float*)d_in[6];
    const float* b1       = (const float*)d_in[7];
    const float* cell_emb = (const float*)d_in[8];
    const float* W2       = (const float*)d_in[9];
    const float* b2       = (const float*)d_in[10];
    float* out = (float*)d_out;

    cudaFuncSetAttribute(k1_maxpool,
                         cudaFuncAttributeMaxDynamicSharedMemorySize, K1_SMEM);
    cudaFuncSetAttribute(k2_appnp,
                         cudaFuncAttributeMaxDynamicSharedMemorySize, K2_SMEM_BYTES);
    cudaFuncSetAttribute(k3_out,
                         cudaFuncAttributeMaxDynamicSharedMemorySize, K3_SMEM);

    k1_maxpool<<<NCHUNK, 1024, K1_SMEM>>>(tgt, M);

    cudaLaunchAttribute pdl[1];
    pdl[0].id = cudaLaunchAttributeProgrammaticStreamSerialization;
    pdl[0].val.programmaticStreamSerializationAllowed = 1;

    {
        cudaLaunchConfig_t cfg = {};
        cfg.gridDim = dim3(B, 1, 1);
        cfg.blockDim = dim3(512, 1, 1);
        cfg.dynamicSmemBytes = K2_SMEM_BYTES;
        cfg.attrs = pdl;
        cfg.numAttrs = 1;
        cudaLaunchKernelEx(&cfg, k2_appnp, A, cell_idx, cell_emb, W2, b2);
    }
    {
        cudaLaunchConfig_t cfg = {};
        cfg.gridDim = dim3((G + GT - 1) / GT, 1, 1);   // 125
        cfg.blockDim = dim3(1024, 1, 1);
        cfg.dynamicSmemBytes = K3_SMEM;
        cfg.attrs = pdl;
        cfg.numAttrs = 1;
        cudaLaunchKernelEx(&cfg, k3_out, ctl, tgt, M, W1, b1, W2, out);
    }
}